// round 1
// baseline (speedup 1.0000x reference)
#include <cuda_runtime.h>
#include <math.h>

#define NU   2560
#define NI   3584
#define NTOT 6144
#define EDIM 64
#define DQK  256
#define KTOP 5

// ---- device scratch (no allocations allowed) ----
__device__ float g_ego0[NTOT*EDIM];
__device__ float g_ego1[NTOT*EDIM];
__device__ float g_ego2[NTOT*EDIM];
__device__ float g_B   [NTOT*EDIM];
__device__ int   g_topk[NTOT*KTOP];
__device__ float g_q [NTOT*DQK];
__device__ float g_kk[NTOT*KTOP*DQK];
__device__ float g_vv[NTOT*KTOP*DQK];

// ---------------------------------------------------------------------------
// ego0 = concat(user, item); zero accumulators
__global__ void init_kernel(const float* __restrict__ ue, const float* __restrict__ ie) {
    int i = blockIdx.x * blockDim.x + threadIdx.x;
    if (i < NTOT*EDIM) {
        g_ego0[i] = (i < NU*EDIM) ? ue[i] : ie[i - NU*EDIM];
        g_ego1[i] = 0.f;
        g_ego2[i] = 0.f;
    }
}

// dst[row] += scale * val * src[col]   (COO, duplicate-accumulating)
__global__ void spmm_atomic(const int* __restrict__ rows, const int* __restrict__ cols,
                            const float* __restrict__ vals,
                            const float* __restrict__ src, float* __restrict__ dst,
                            float scale, int nnz) {
    int t = blockIdx.x * blockDim.x + threadIdx.x;
    int nz = t >> 6;
    if (nz >= nnz) return;
    int e = t & 63;
    float v = vals[nz] * scale;
    atomicAdd(&dst[rows[nz]*EDIM + e], v * src[cols[nz]*EDIM + e]);
}

// mean of [ego0, ego1]
__global__ void mean_kernel(float* __restrict__ out) {
    int i = blockIdx.x * blockDim.x + threadIdx.x;
    if (i < NTOT*EDIM) out[i] = 0.5f * (g_ego0[i] + g_ego1[i]);
}

// B = ego2 (then spmm adds 0.5*A*ego2)
__global__ void copyB_kernel() {
    int i = blockIdx.x * blockDim.x + threadIdx.x;
    if (i < NTOT*EDIM) g_B[i] = g_ego2[i];
}

// ---------------------------------------------------------------------------
// Fused sim GEMM + per-row top-5:  sim[i][j] = B[i,:]·ego2[j,:]
// Block: 256 thr, TM=32 rows, TJ=128 cols/chunk, per-thread 4x4 accumulators.
// Tie-break matches jax.lax.top_k: (value desc, index asc).
__global__ __launch_bounds__(256) void topk_kernel() {
    const int TM = 32, TJ = 128;
    __shared__ float BsT[EDIM][TM + 1];   // e-major
    __shared__ float EsT[EDIM][TJ + 1];   // e-major

    int tid  = threadIdx.x;
    int row0 = blockIdx.x * TM;

    for (int idx = tid; idx < TM*EDIM; idx += 256) {
        int r = idx >> 6, e = idx & 63;
        BsT[e][r] = g_B[(row0 + r)*EDIM + e];
    }

    int ty = tid >> 5;   // warp id = row group (4 rows)
    int tx = tid & 31;   // lane    = col lane  (4 cols, stride 32)

    float tv[4][KTOP];
    int   tix[4][KTOP];
#pragma unroll
    for (int i = 0; i < 4; i++)
#pragma unroll
        for (int s = 0; s < KTOP; s++) { tv[i][s] = -INFINITY; tix[i][s] = 0x7fffffff; }

    for (int chunk = 0; chunk < NTOT; chunk += TJ) {
        __syncthreads();
        for (int idx = tid; idx < TJ*EDIM; idx += 256) {
            int j = idx >> 6, e = idx & 63;
            EsT[e][j] = g_ego2[(chunk + j)*EDIM + e];
        }
        __syncthreads();

        float acc[4][4];
#pragma unroll
        for (int i = 0; i < 4; i++)
#pragma unroll
            for (int jj = 0; jj < 4; jj++) acc[i][jj] = 0.f;

#pragma unroll 8
        for (int e = 0; e < EDIM; e++) {
            float a0 = BsT[e][ty*4 + 0];
            float a1 = BsT[e][ty*4 + 1];
            float a2 = BsT[e][ty*4 + 2];
            float a3 = BsT[e][ty*4 + 3];
            float b0 = EsT[e][tx];
            float b1 = EsT[e][tx + 32];
            float b2 = EsT[e][tx + 64];
            float b3 = EsT[e][tx + 96];
            acc[0][0] += a0*b0; acc[0][1] += a0*b1; acc[0][2] += a0*b2; acc[0][3] += a0*b3;
            acc[1][0] += a1*b0; acc[1][1] += a1*b1; acc[1][2] += a1*b2; acc[1][3] += a1*b3;
            acc[2][0] += a2*b0; acc[2][1] += a2*b1; acc[2][2] += a2*b2; acc[2][3] += a2*b3;
            acc[3][0] += a3*b0; acc[3][1] += a3*b1; acc[3][2] += a3*b2; acc[3][3] += a3*b3;
        }

        // update per-thread top-5 (j ascending -> strict > keeps smallest index on ties)
#pragma unroll
        for (int i = 0; i < 4; i++) {
#pragma unroll
            for (int jj = 0; jj < 4; jj++) {
                float v = acc[i][jj];
                int   j = chunk + jj*32 + tx;
                if (v > tv[i][KTOP-1]) {
                    tv[i][KTOP-1] = v; tix[i][KTOP-1] = j;
#pragma unroll
                    for (int p = KTOP-1; p > 0; p--) {
                        if (tv[i][p] > tv[i][p-1]) {
                            float fv = tv[i][p]; tv[i][p] = tv[i][p-1]; tv[i][p-1] = fv;
                            int   fi = tix[i][p]; tix[i][p] = tix[i][p-1]; tix[i][p-1] = fi;
                        }
                    }
                }
            }
        }
    }

    // warp-level merge: one warp owns 4 rows, candidates live across its 32 lanes
#pragma unroll
    for (int i = 0; i < 4; i++) {
        int p = 0;
        for (int s = 0; s < KTOP; s++) {
            float v = (p < KTOP) ? tv[i][p]  : -INFINITY;
            int   j = (p < KTOP) ? tix[i][p] : 0x7fffffff;
            float bv = v; int bj = j;
#pragma unroll
            for (int off = 16; off; off >>= 1) {
                float ov = __shfl_xor_sync(0xffffffffu, bv, off);
                int   oj = __shfl_xor_sync(0xffffffffu, bj, off);
                if (ov > bv || (ov == bv && oj < bj)) { bv = ov; bj = oj; }
            }
            if (bj == j && bv == v && p < KTOP) p++;   // unique j -> unique owner
            if (tx == 0) g_topk[(row0 + ty*4 + i)*KTOP + s] = bj;
        }
    }
}

// ---------------------------------------------------------------------------
// Y[m][0..255] = bias + X[src(m),:] @ W^T      (K=64)
// Block: 256 thr, 64 rows, 4 chunks of 64 cols.
__global__ __launch_bounds__(256) void gemm64_kernel(const float* __restrict__ X,
                                                     const int* __restrict__ gather,
                                                     const float* __restrict__ W,
                                                     const float* __restrict__ bias,
                                                     float* __restrict__ Y) {
    __shared__ float XsT[EDIM][65];
    __shared__ float WsT[EDIM][65];
    int tid  = threadIdx.x;
    int row0 = blockIdx.x * 64;

    for (int idx = tid; idx < 64*EDIM; idx += 256) {
        int r = idx >> 6, e = idx & 63;
        int src = row0 + r;
        int srow = gather ? gather[src] : src;
        XsT[e][r] = X[srow*EDIM + e];
    }

    int ty = tid >> 4;   // 16 groups x 4 rows
    int tx = tid & 15;   // 16 lanes  x 4 cols (stride 16)

    for (int cc = 0; cc < 4; cc++) {
        __syncthreads();
        for (int idx = tid; idx < 64*EDIM; idx += 256) {
            int c = idx >> 6, e = idx & 63;
            WsT[e][c] = W[(cc*64 + c)*EDIM + e];
        }
        __syncthreads();

        float acc[4][4];
#pragma unroll
        for (int i = 0; i < 4; i++)
#pragma unroll
            for (int j = 0; j < 4; j++) acc[i][j] = bias[cc*64 + j*16 + tx];

#pragma unroll 8
        for (int e = 0; e < EDIM; e++) {
            float a0 = XsT[e][ty*4 + 0];
            float a1 = XsT[e][ty*4 + 1];
            float a2 = XsT[e][ty*4 + 2];
            float a3 = XsT[e][ty*4 + 3];
            float w0 = WsT[e][tx];
            float w1 = WsT[e][tx + 16];
            float w2 = WsT[e][tx + 32];
            float w3 = WsT[e][tx + 48];
            acc[0][0] += a0*w0; acc[0][1] += a0*w1; acc[0][2] += a0*w2; acc[0][3] += a0*w3;
            acc[1][0] += a1*w0; acc[1][1] += a1*w1; acc[1][2] += a1*w2; acc[1][3] += a1*w3;
            acc[2][0] += a2*w0; acc[2][1] += a2*w1; acc[2][2] += a2*w2; acc[2][3] += a2*w3;
            acc[3][0] += a3*w0; acc[3][1] += a3*w1; acc[3][2] += a3*w2; acc[3][3] += a3*w3;
        }

#pragma unroll
        for (int i = 0; i < 4; i++)
#pragma unroll
            for (int j = 0; j < 4; j++)
                Y[(row0 + ty*4 + i)*DQK + cc*64 + j*16 + tx] = acc[i][j];
    }
}

// ---------------------------------------------------------------------------
// scores -> softmax -> weighted sum of V.  One warp per node row.
__global__ __launch_bounds__(256) void attn_kernel(float* __restrict__ out) {
    int gw   = (blockIdx.x * 256 + threadIdx.x) >> 5;
    int lane = threadIdx.x & 31;
    if (gw >= NTOT) return;

    const float4* q4 = (const float4*)(g_q + gw*DQK);
    float4 qa = q4[lane*2], qb = q4[lane*2 + 1];

    float s[KTOP];
#pragma unroll
    for (int k = 0; k < KTOP; k++) {
        const float4* k4 = (const float4*)(g_kk + (gw*KTOP + k)*DQK);
        float4 ka = k4[lane*2], kb = k4[lane*2 + 1];
        float p = qa.x*ka.x + qa.y*ka.y + qa.z*ka.z + qa.w*ka.w
                + qb.x*kb.x + qb.y*kb.y + qb.z*kb.z + qb.w*kb.w;
#pragma unroll
        for (int off = 16; off; off >>= 1) p += __shfl_xor_sync(0xffffffffu, p, off);
        s[k] = p * (1.0f / 16.0f);    // 1/sqrt(256)
    }

    float m = s[0];
#pragma unroll
    for (int k = 1; k < KTOP; k++) m = fmaxf(m, s[k]);
    float esum = 0.f;
#pragma unroll
    for (int k = 0; k < KTOP; k++) { s[k] = expf(s[k] - m); esum += s[k]; }
    float inv = 1.f / esum;

    float4 oa = make_float4(0.f,0.f,0.f,0.f), ob = make_float4(0.f,0.f,0.f,0.f);
#pragma unroll
    for (int k = 0; k < KTOP; k++) {
        const float4* v4 = (const float4*)(g_vv + (gw*KTOP + k)*DQK);
        float4 va = v4[lane*2], vb = v4[lane*2 + 1];
        float a = s[k] * inv;
        oa.x += a*va.x; oa.y += a*va.y; oa.z += a*va.z; oa.w += a*va.w;
        ob.x += a*vb.x; ob.y += a*vb.y; ob.z += a*vb.z; ob.w += a*vb.w;
    }
    float4* o4 = (float4*)(out + gw*DQK);
    o4[lane*2] = oa; o4[lane*2 + 1] = ob;
}

// ---------------------------------------------------------------------------
extern "C" void kernel_launch(void* const* d_in, const int* in_sizes, int n_in,
                              void* d_out, int out_size) {
    const float* ue = (const float*)d_in[0];
    const float* ie = (const float*)d_in[1];
    const int*   nr = (const int*)d_in[2];
    const int*   nc = (const int*)d_in[3];
    const float* nv = (const float*)d_in[4];
    const int*   ar = (const int*)d_in[5];
    const int*   ac = (const int*)d_in[6];
    const float* av = (const float*)d_in[7];
    const float* Wq = (const float*)d_in[8];
    const float* bq = (const float*)d_in[9];
    const float* Wk = (const float*)d_in[10];
    const float* bk = (const float*)d_in[11];
    const float* Wv = (const float*)d_in[12];
    const float* bv = (const float*)d_in[13];
    float* out = (float*)d_out;

    int nnz = in_sizes[2];
    int ew_blocks   = (NTOT*EDIM + 255) / 256;
    int spmm_blocks = (nnz*64 + 255) / 256;

    float *ego0, *ego1, *ego2, *B, *q, *kk, *vv;
    int *topk;
    cudaGetSymbolAddress((void**)&ego0, g_ego0);
    cudaGetSymbolAddress((void**)&ego1, g_ego1);
    cudaGetSymbolAddress((void**)&ego2, g_ego2);
    cudaGetSymbolAddress((void**)&B,    g_B);
    cudaGetSymbolAddress((void**)&q,    g_q);
    cudaGetSymbolAddress((void**)&kk,   g_kk);
    cudaGetSymbolAddress((void**)&vv,   g_vv);
    cudaGetSymbolAddress((void**)&topk, g_topk);

    init_kernel<<<ew_blocks, 256>>>(ue, ie);
    // ego1 = A_norm @ ego0
    spmm_atomic<<<spmm_blocks, 256>>>(nr, nc, nv, ego0, ego1, 1.0f, nnz);
    // mean output (layers = [ego0, ego1])
    mean_kernel<<<ew_blocks, 256>>>(out);
    // ego2 = A_norm @ ego1
    spmm_atomic<<<spmm_blocks, 256>>>(nr, nc, nv, ego1, ego2, 1.0f, nnz);
    // B = ego2 + 0.5 * A @ ego2
    copyB_kernel<<<ew_blocks, 256>>>();
    spmm_atomic<<<spmm_blocks, 256>>>(ar, ac, av, ego2, B, 0.5f, nnz);
    // fused sim + top-5
    topk_kernel<<<NTOT/32, 256>>>();
    // Q / K / V projections (K,V gathered by topk indices)
    gemm64_kernel<<<NTOT/64, 256>>>(ego2, nullptr, Wq, bq, q);
    gemm64_kernel<<<NTOT*KTOP/64, 256>>>(ego2, topk, Wk, bk, kk);
    gemm64_kernel<<<NTOT*KTOP/64, 256>>>(ego2, topk, Wv, bv, vv);
    // softmax attention epilogue
    attn_kernel<<<(NTOT*32 + 255)/256, 256>>>(out + NTOT*EDIM);
}

// round 2
// speedup vs baseline: 1.5171x; 1.5171x over previous
#include <cuda_runtime.h>
#include <math.h>

#define NU   2560
#define NI   3584
#define NTOT 6144
#define EDIM 64
#define DQK  256
#define KTOP 5
#define RS   66          // padded smem row stride (floats): conflict-free for LDS.64

// ---- device scratch ----
__device__ float g_ego0[NTOT*EDIM];
__device__ float g_ego1[NTOT*EDIM];
__device__ float g_ego2[NTOT*EDIM];
__device__ float g_B   [NTOT*EDIM];
__device__ int   g_topk[NTOT*KTOP];
__device__ float g_q [NTOT*DQK];
__device__ float g_k [NTOT*DQK];
__device__ float g_v [NTOT*DQK];

typedef unsigned long long ull;

__device__ __forceinline__ ull fma2(ull a, ull b, ull c) {
    ull d;
    asm("fma.rn.f32x2 %0, %1, %2, %3;" : "=l"(d) : "l"(a), "l"(b), "l"(c));
    return d;
}
__device__ __forceinline__ float pairsum(ull p) {
    return __uint_as_float((unsigned)p) + __uint_as_float((unsigned)(p >> 32));
}

// ---------------------------------------------------------------------------
__global__ void init_kernel(const float* __restrict__ ue, const float* __restrict__ ie) {
    int i = blockIdx.x * blockDim.x + threadIdx.x;
    if (i < NTOT*EDIM) {
        g_ego0[i] = (i < NU*EDIM) ? ue[i] : ie[i - NU*EDIM];
        g_ego1[i] = 0.f;
        g_ego2[i] = 0.f;
    }
}

// dst[row] += scale * val * src[col]  — 16 threads/nnz, vectorized red.v4
__global__ void spmm_atomic(const int* __restrict__ rows, const int* __restrict__ cols,
                            const float* __restrict__ vals,
                            const float* __restrict__ src, float* __restrict__ dst,
                            float scale, int nnz) {
    int t = blockIdx.x * blockDim.x + threadIdx.x;
    int nz = t >> 4;
    if (nz >= nnz) return;
    int e = (t & 15) * 4;
    float v = vals[nz] * scale;
    float4 s = *(const float4*)&src[cols[nz]*EDIM + e];
    float* d = &dst[rows[nz]*EDIM + e];
    asm volatile("red.global.add.v4.f32 [%0], {%1,%2,%3,%4};"
                 :: "l"(d), "f"(v*s.x), "f"(v*s.y), "f"(v*s.z), "f"(v*s.w) : "memory");
}

__global__ void mean_kernel(float* __restrict__ out) {
    int i = blockIdx.x * blockDim.x + threadIdx.x;
    if (i < NTOT*EDIM) out[i] = 0.5f * (g_ego0[i] + g_ego1[i]);
}

__global__ void copyB_kernel() {
    int i = blockIdx.x * blockDim.x + threadIdx.x;
    if (i < NTOT*EDIM) g_B[i] = g_ego2[i];
}

// ---------------------------------------------------------------------------
// Fused sim GEMM + per-row top-5, K-packed fma.rn.f32x2.
// 256 thr, TM=32 rows/block, TJ=128 cols/chunk, per-thread 4x4.
// Tie-break matches jax.lax.top_k: (value desc, index asc).
__global__ __launch_bounds__(256) void topk_kernel() {
    const int TM = 32, TJ = 128;
    __shared__ float Bs[TM*RS];
    __shared__ float Es[TJ*RS];

    int tid  = threadIdx.x;
    int tx   = tid & 31;
    int w    = tid >> 5;         // warp = 4-row group
    int row0 = blockIdx.x * TM;

    for (int idx = tid; idx < TM*32; idx += 256) {
        int r = idx >> 5, e2 = idx & 31;
        *(float2*)&Bs[r*RS + 2*e2] = *(const float2*)&g_B[(row0 + r)*EDIM + 2*e2];
    }

    float tv[4][KTOP];
    int   ti[4][KTOP];
#pragma unroll
    for (int i = 0; i < 4; i++)
#pragma unroll
        for (int s = 0; s < KTOP; s++) { tv[i][s] = -INFINITY; ti[i][s] = 0x7fffffff; }

    for (int chunk = 0; chunk < NTOT; chunk += TJ) {
        __syncthreads();
        for (int idx = tid; idx < TJ*32; idx += 256) {
            int j = idx >> 5, e2 = idx & 31;
            *(float2*)&Es[j*RS + 2*e2] = *(const float2*)&g_ego2[(chunk + j)*EDIM + 2*e2];
        }
        __syncthreads();

        ull acc[4][4];
#pragma unroll
        for (int i = 0; i < 4; i++)
#pragma unroll
            for (int c = 0; c < 4; c++) acc[i][c] = 0ull;

#pragma unroll 8
        for (int e2 = 0; e2 < 32; e2++) {
            ull a0 = *(const ull*)&Bs[(w*4 + 0)*RS + 2*e2];
            ull a1 = *(const ull*)&Bs[(w*4 + 1)*RS + 2*e2];
            ull a2 = *(const ull*)&Bs[(w*4 + 2)*RS + 2*e2];
            ull a3 = *(const ull*)&Bs[(w*4 + 3)*RS + 2*e2];
            ull b0 = *(const ull*)&Es[(tx +  0)*RS + 2*e2];
            ull b1 = *(const ull*)&Es[(tx + 32)*RS + 2*e2];
            ull b2 = *(const ull*)&Es[(tx + 64)*RS + 2*e2];
            ull b3 = *(const ull*)&Es[(tx + 96)*RS + 2*e2];
            acc[0][0]=fma2(a0,b0,acc[0][0]); acc[0][1]=fma2(a0,b1,acc[0][1]);
            acc[0][2]=fma2(a0,b2,acc[0][2]); acc[0][3]=fma2(a0,b3,acc[0][3]);
            acc[1][0]=fma2(a1,b0,acc[1][0]); acc[1][1]=fma2(a1,b1,acc[1][1]);
            acc[1][2]=fma2(a1,b2,acc[1][2]); acc[1][3]=fma2(a1,b3,acc[1][3]);
            acc[2][0]=fma2(a2,b0,acc[2][0]); acc[2][1]=fma2(a2,b1,acc[2][1]);
            acc[2][2]=fma2(a2,b2,acc[2][2]); acc[2][3]=fma2(a2,b3,acc[2][3]);
            acc[3][0]=fma2(a3,b0,acc[3][0]); acc[3][1]=fma2(a3,b1,acc[3][1]);
            acc[3][2]=fma2(a3,b2,acc[3][2]); acc[3][3]=fma2(a3,b3,acc[3][3]);
        }

        // top-5 insert; j ascending across chunks, strict > keeps smallest index on ties
#pragma unroll
        for (int i = 0; i < 4; i++) {
#pragma unroll
            for (int c = 0; c < 4; c++) {
                float vv = pairsum(acc[i][c]);
                int   j  = chunk + tx + 32*c;
                if (vv > tv[i][KTOP-1]) {
                    tv[i][KTOP-1] = vv; ti[i][KTOP-1] = j;
#pragma unroll
                    for (int p = KTOP-1; p > 0; p--) {
                        if (tv[i][p] > tv[i][p-1]) {
                            float fv = tv[i][p]; tv[i][p] = tv[i][p-1]; tv[i][p-1] = fv;
                            int   fi = ti[i][p]; ti[i][p] = ti[i][p-1]; ti[i][p-1] = fi;
                        }
                    }
                }
            }
        }
    }

    // warp-level merge: warp owns 4 rows; candidates across its 32 lanes
#pragma unroll
    for (int i = 0; i < 4; i++) {
        int p = 0;
        for (int s = 0; s < KTOP; s++) {
            float v = (p < KTOP) ? tv[i][p] : -INFINITY;
            int   j = (p < KTOP) ? ti[i][p] : 0x7fffffff;
            float bv = v; int bj = j;
#pragma unroll
            for (int off = 16; off; off >>= 1) {
                float ov = __shfl_xor_sync(0xffffffffu, bv, off);
                int   oj = __shfl_xor_sync(0xffffffffu, bj, off);
                if (ov > bv || (ov == bv && oj < bj)) { bv = ov; bj = oj; }
            }
            if (bj == j && bv == v && p < KTOP) p++;
            if (tx == 0) g_topk[(row0 + w*4 + i)*KTOP + s] = bj;
        }
    }
}

// ---------------------------------------------------------------------------
// Fused Q/K/V projections for ALL nodes (gather happens later in attn).
// Y = ego2 @ W^T + b,  K=64, K-packed f32x2. blockIdx.y selects {Q,K,V}.
__global__ __launch_bounds__(256) void qkv_kernel(
    const float* __restrict__ Wq, const float* __restrict__ bq,
    const float* __restrict__ Wk, const float* __restrict__ bk,
    const float* __restrict__ Wv, const float* __restrict__ bv) {
    __shared__ float Xs[64*RS];
    __shared__ float Ws[64*RS];

    const float *W, *bias; float* Y;
    if (blockIdx.y == 0)      { W = Wq; bias = bq; Y = g_q; }
    else if (blockIdx.y == 1) { W = Wk; bias = bk; Y = g_k; }
    else                      { W = Wv; bias = bv; Y = g_v; }

    int tid  = threadIdx.x;
    int txc  = tid & 15;     // 16 lanes x 4 cols (stride 16)
    int ty   = tid >> 4;     // 16 groups x 4 rows
    int row0 = blockIdx.x * 64;

    for (int idx = tid; idx < 64*32; idx += 256) {
        int r = idx >> 5, e2 = idx & 31;
        *(float2*)&Xs[r*RS + 2*e2] = *(const float2*)&g_ego2[(row0 + r)*EDIM + 2*e2];
    }

    for (int cc = 0; cc < 4; cc++) {
        __syncthreads();
        for (int idx = tid; idx < 64*32; idx += 256) {
            int c = idx >> 5, e2 = idx & 31;
            *(float2*)&Ws[c*RS + 2*e2] = *(const float2*)&W[(cc*64 + c)*EDIM + 2*e2];
        }
        __syncthreads();

        ull acc[4][4];
#pragma unroll
        for (int i = 0; i < 4; i++)
#pragma unroll
            for (int c = 0; c < 4; c++) acc[i][c] = 0ull;

#pragma unroll 8
        for (int e2 = 0; e2 < 32; e2++) {
            ull a0 = *(const ull*)&Xs[(ty*4 + 0)*RS + 2*e2];
            ull a1 = *(const ull*)&Xs[(ty*4 + 1)*RS + 2*e2];
            ull a2 = *(const ull*)&Xs[(ty*4 + 2)*RS + 2*e2];
            ull a3 = *(const ull*)&Xs[(ty*4 + 3)*RS + 2*e2];
            ull b0 = *(const ull*)&Ws[(txc +  0)*RS + 2*e2];
            ull b1 = *(const ull*)&Ws[(txc + 16)*RS + 2*e2];
            ull b2 = *(const ull*)&Ws[(txc + 32)*RS + 2*e2];
            ull b3 = *(const ull*)&Ws[(txc + 48)*RS + 2*e2];
            acc[0][0]=fma2(a0,b0,acc[0][0]); acc[0][1]=fma2(a0,b1,acc[0][1]);
            acc[0][2]=fma2(a0,b2,acc[0][2]); acc[0][3]=fma2(a0,b3,acc[0][3]);
            acc[1][0]=fma2(a1,b0,acc[1][0]); acc[1][1]=fma2(a1,b1,acc[1][1]);
            acc[1][2]=fma2(a1,b2,acc[1][2]); acc[1][3]=fma2(a1,b3,acc[1][3]);
            acc[2][0]=fma2(a2,b0,acc[2][0]); acc[2][1]=fma2(a2,b1,acc[2][1]);
            acc[2][2]=fma2(a2,b2,acc[2][2]); acc[2][3]=fma2(a2,b3,acc[2][3]);
            acc[3][0]=fma2(a3,b0,acc[3][0]); acc[3][1]=fma2(a3,b1,acc[3][1]);
            acc[3][2]=fma2(a3,b2,acc[3][2]); acc[3][3]=fma2(a3,b3,acc[3][3]);
        }

#pragma unroll
        for (int i = 0; i < 4; i++)
#pragma unroll
            for (int c = 0; c < 4; c++) {
                int col = cc*64 + txc + 16*c;
                Y[(row0 + ty*4 + i)*DQK + col] = pairsum(acc[i][c]) + bias[col];
            }
    }
}

// ---------------------------------------------------------------------------
// Gather K/V rows via top-k, softmax over 5 scores, weighted V sum.
// One warp per node row.
__global__ __launch_bounds__(256) void attn_kernel(float* __restrict__ out) {
    int gw   = (blockIdx.x * 256 + threadIdx.x) >> 5;
    int lane = threadIdx.x & 31;
    if (gw >= NTOT) return;

    int idx[KTOP];
#pragma unroll
    for (int k = 0; k < KTOP; k++) idx[k] = g_topk[gw*KTOP + k];

    const float4* q4 = (const float4*)(g_q + gw*DQK);
    float4 qa = q4[lane*2], qb = q4[lane*2 + 1];

    float s[KTOP];
#pragma unroll
    for (int k = 0; k < KTOP; k++) {
        const float4* k4 = (const float4*)(g_k + idx[k]*DQK);
        float4 ka = k4[lane*2], kb = k4[lane*2 + 1];
        float p = qa.x*ka.x + qa.y*ka.y + qa.z*ka.z + qa.w*ka.w
                + qb.x*kb.x + qb.y*kb.y + qb.z*kb.z + qb.w*kb.w;
#pragma unroll
        for (int off = 16; off; off >>= 1) p += __shfl_xor_sync(0xffffffffu, p, off);
        s[k] = p * (1.0f / 16.0f);   // 1/sqrt(256)
    }

    float m = s[0];
#pragma unroll
    for (int k = 1; k < KTOP; k++) m = fmaxf(m, s[k]);
    float esum = 0.f;
#pragma unroll
    for (int k = 0; k < KTOP; k++) { s[k] = expf(s[k] - m); esum += s[k]; }
    float inv = 1.f / esum;

    float4 oa = make_float4(0.f,0.f,0.f,0.f), ob = make_float4(0.f,0.f,0.f,0.f);
#pragma unroll
    for (int k = 0; k < KTOP; k++) {
        const float4* v4 = (const float4*)(g_v + idx[k]*DQK);
        float4 va = v4[lane*2], vb = v4[lane*2 + 1];
        float a = s[k] * inv;
        oa.x += a*va.x; oa.y += a*va.y; oa.z += a*va.z; oa.w += a*va.w;
        ob.x += a*vb.x; ob.y += a*vb.y; ob.z += a*vb.z; ob.w += a*vb.w;
    }
    float4* o4 = (float4*)(out + gw*DQK);
    o4[lane*2] = oa; o4[lane*2 + 1] = ob;
}

// ---------------------------------------------------------------------------
extern "C" void kernel_launch(void* const* d_in, const int* in_sizes, int n_in,
                              void* d_out, int out_size) {
    const float* ue = (const float*)d_in[0];
    const float* ie = (const float*)d_in[1];
    const int*   nr = (const int*)d_in[2];
    const int*   nc = (const int*)d_in[3];
    const float* nv = (const float*)d_in[4];
    const int*   ar = (const int*)d_in[5];
    const int*   ac = (const int*)d_in[6];
    const float* av = (const float*)d_in[7];
    const float* Wq = (const float*)d_in[8];
    const float* bq = (const float*)d_in[9];
    const float* Wk = (const float*)d_in[10];
    const float* bk = (const float*)d_in[11];
    const float* Wv = (const float*)d_in[12];
    const float* bv = (const float*)d_in[13];
    float* out = (float*)d_out;

    int nnz = in_sizes[2];
    int ew_blocks   = (NTOT*EDIM + 255) / 256;
    int spmm_blocks = (nnz*16 + 255) / 256;

    float *ego0, *ego1, *ego2, *B;
    int *topk;
    cudaGetSymbolAddress((void**)&ego0, g_ego0);
    cudaGetSymbolAddress((void**)&ego1, g_ego1);
    cudaGetSymbolAddress((void**)&ego2, g_ego2);
    cudaGetSymbolAddress((void**)&B,    g_B);
    cudaGetSymbolAddress((void**)&topk, g_topk);

    init_kernel<<<ew_blocks, 256>>>(ue, ie);
    spmm_atomic<<<spmm_blocks, 256>>>(nr, nc, nv, ego0, ego1, 1.0f, nnz);  // ego1 = An@ego0
    mean_kernel<<<ew_blocks, 256>>>(out);                                   // mean(ego0,ego1)
    spmm_atomic<<<spmm_blocks, 256>>>(nr, nc, nv, ego1, ego2, 1.0f, nnz);  // ego2 = An@ego1
    copyB_kernel<<<ew_blocks, 256>>>();                                     // B = ego2
    spmm_atomic<<<spmm_blocks, 256>>>(ar, ac, av, ego2, B, 0.5f, nnz);     // B += 0.5*A@ego2
    topk_kernel<<<NTOT/32, 256>>>();                                        // fused sim + top5
    qkv_kernel<<<dim3(NTOT/64, 3), 256>>>(Wq, bq, Wk, bk, Wv, bv);          // Q/K/V all nodes
    attn_kernel<<<(NTOT*32 + 255)/256, 256>>>(out + NTOT*EDIM);             // gather+softmax
}

// round 3
// speedup vs baseline: 1.5236x; 1.0043x over previous
#include <cuda_runtime.h>
#include <math.h>

#define NU   2560
#define NI   3584
#define NTOT 6144
#define EDIM 64
#define DQK  256
#define KTOP 5
#define RS   68          // smem row stride (floats); conflict-free for LDS.128
#define NSPLIT 2
#define TJ   128

// ---- device scratch ----
__device__ float g_ego0[NTOT*EDIM];
__device__ float g_ego1[NTOT*EDIM];
__device__ float g_ego2[NTOT*EDIM];
__device__ float g_B   [NTOT*EDIM];
__device__ int   g_topk[NTOT*KTOP];
__device__ float g_cv[NSPLIT*NTOT*KTOP];
__device__ int   g_cj[NSPLIT*NTOT*KTOP];
__device__ float g_q [NTOT*DQK];
__device__ float g_k [NTOT*DQK];
__device__ float g_v [NTOT*DQK];

typedef unsigned long long ull;

__device__ __forceinline__ ull fma2(ull a, ull b, ull c) {
    ull d;
    asm("fma.rn.f32x2 %0, %1, %2, %3;" : "=l"(d) : "l"(a), "l"(b), "l"(c));
    return d;
}
__device__ __forceinline__ float pairsum(ull p) {
    return __uint_as_float((unsigned)p) + __uint_as_float((unsigned)(p >> 32));
}
__device__ __forceinline__ void cp16(void* dst, const void* src) {
    unsigned s = (unsigned)__cvta_generic_to_shared(dst);
    asm volatile("cp.async.cg.shared.global [%0], [%1], 16;" :: "r"(s), "l"(src) : "memory");
}

// ---------------------------------------------------------------------------
__global__ void init_kernel(const float* __restrict__ ue, const float* __restrict__ ie) {
    int i = blockIdx.x * blockDim.x + threadIdx.x;
    if (i < NTOT*EDIM) {
        g_ego0[i] = (i < NU*EDIM) ? ue[i] : ie[i - NU*EDIM];
        g_ego1[i] = 0.f;
        g_ego2[i] = 0.f;
    }
}

// dst[row] += scale * val * src[col]  — 16 threads/nnz, red.v4
__global__ void spmm_atomic(const int* __restrict__ rows, const int* __restrict__ cols,
                            const float* __restrict__ vals,
                            const float* __restrict__ src, float* __restrict__ dst,
                            float scale, int nnz) {
    int t = blockIdx.x * blockDim.x + threadIdx.x;
    int nz = t >> 4;
    if (nz >= nnz) return;
    int e = (t & 15) * 4;
    float v = vals[nz] * scale;
    float4 s = *(const float4*)&src[cols[nz]*EDIM + e];
    float* d = &dst[rows[nz]*EDIM + e];
    asm volatile("red.global.add.v4.f32 [%0], {%1,%2,%3,%4};"
                 :: "l"(d), "f"(v*s.x), "f"(v*s.y), "f"(v*s.z), "f"(v*s.w) : "memory");
}

__global__ void mean_kernel(float* __restrict__ out) {
    int i = blockIdx.x * blockDim.x + threadIdx.x;
    if (i < NTOT*EDIM) out[i] = 0.5f * (g_ego0[i] + g_ego1[i]);
}

__global__ void copyB_kernel() {
    int i = blockIdx.x * blockDim.x + threadIdx.x;
    if (i < NTOT*EDIM) g_B[i] = g_ego2[i];
}

// ---------------------------------------------------------------------------
// Fused sim GEMM + per-row top-5 over one j-half. 32 rows/block, TJ=128 cols
// per chunk, per-thread 4x4, LDS.128, cp.async double-buffered Es.
__global__ __launch_bounds__(256, 2) void topk_pass() {
    __shared__ float Bs[32*RS];
    extern __shared__ float Es[];       // 2 * TJ * RS floats

    int tid  = threadIdx.x;
    int tx   = tid & 31;
    int w    = tid >> 5;                 // warp = 4-row group
    int row0 = blockIdx.x * 32;
    int jbase = blockIdx.y * (NTOT / NSPLIT);
    const int NCH = (NTOT / NSPLIT) / TJ;   // 24

    for (int idx = tid; idx < 32*16; idx += 256) {
        int r = idx >> 4, q2 = idx & 15;
        *(float4*)&Bs[r*RS + q2*4] = *(const float4*)&g_B[(row0 + r)*EDIM + q2*4];
    }

    // prefetch chunk 0
    for (int idx = tid; idx < TJ*16; idx += 256) {
        int c = idx >> 4, q2 = idx & 15;
        cp16(&Es[c*RS + q2*4], &g_ego2[(jbase + c)*EDIM + q2*4]);
    }
    asm volatile("cp.async.commit_group;");

    float tv[4][KTOP];
    int   ti[4][KTOP];
#pragma unroll
    for (int i = 0; i < 4; i++)
#pragma unroll
        for (int s = 0; s < KTOP; s++) { tv[i][s] = -INFINITY; ti[i][s] = 0x7fffffff; }

    for (int k = 0; k < NCH; k++) {
        int cur = (k & 1) * TJ * RS;
        if (k + 1 < NCH) {
            int nxt = ((k + 1) & 1) * TJ * RS;
            int jn = jbase + (k + 1) * TJ;
            for (int idx = tid; idx < TJ*16; idx += 256) {
                int c = idx >> 4, q2 = idx & 15;
                cp16(&Es[nxt + c*RS + q2*4], &g_ego2[(jn + c)*EDIM + q2*4]);
            }
            asm volatile("cp.async.commit_group;");
            asm volatile("cp.async.wait_group 1;");
        } else {
            asm volatile("cp.async.wait_group 0;");
        }
        __syncthreads();

        ull acc[4][4];
#pragma unroll
        for (int i = 0; i < 4; i++)
#pragma unroll
            for (int c = 0; c < 4; c++) acc[i][c] = 0ull;

#pragma unroll 4
        for (int u = 0; u < 16; u++) {      // 4 K-floats per step
            float4 a0 = *(const float4*)&Bs[(w*4 + 0)*RS + u*4];
            float4 a1 = *(const float4*)&Bs[(w*4 + 1)*RS + u*4];
            float4 a2 = *(const float4*)&Bs[(w*4 + 2)*RS + u*4];
            float4 a3 = *(const float4*)&Bs[(w*4 + 3)*RS + u*4];
            float4 b0 = *(const float4*)&Es[cur + (tx +  0)*RS + u*4];
            float4 b1 = *(const float4*)&Es[cur + (tx + 32)*RS + u*4];
            float4 b2 = *(const float4*)&Es[cur + (tx + 64)*RS + u*4];
            float4 b3 = *(const float4*)&Es[cur + (tx + 96)*RS + u*4];
            const ull* A0 = (const ull*)&a0; const ull* A1 = (const ull*)&a1;
            const ull* A2 = (const ull*)&a2; const ull* A3 = (const ull*)&a3;
            const ull* B0 = (const ull*)&b0; const ull* B1 = (const ull*)&b1;
            const ull* B2 = (const ull*)&b2; const ull* B3 = (const ull*)&b3;
#pragma unroll
            for (int h = 0; h < 2; h++) {
                acc[0][0]=fma2(A0[h],B0[h],acc[0][0]); acc[0][1]=fma2(A0[h],B1[h],acc[0][1]);
                acc[0][2]=fma2(A0[h],B2[h],acc[0][2]); acc[0][3]=fma2(A0[h],B3[h],acc[0][3]);
                acc[1][0]=fma2(A1[h],B0[h],acc[1][0]); acc[1][1]=fma2(A1[h],B1[h],acc[1][1]);
                acc[1][2]=fma2(A1[h],B2[h],acc[1][2]); acc[1][3]=fma2(A1[h],B3[h],acc[1][3]);
                acc[2][0]=fma2(A2[h],B0[h],acc[2][0]); acc[2][1]=fma2(A2[h],B1[h],acc[2][1]);
                acc[2][2]=fma2(A2[h],B2[h],acc[2][2]); acc[2][3]=fma2(A2[h],B3[h],acc[2][3]);
                acc[3][0]=fma2(A3[h],B0[h],acc[3][0]); acc[3][1]=fma2(A3[h],B1[h],acc[3][1]);
                acc[3][2]=fma2(A3[h],B2[h],acc[3][2]); acc[3][3]=fma2(A3[h],B3[h],acc[3][3]);
            }
        }

        // top-5 insert; j ascending -> strict > keeps smallest index on ties
#pragma unroll
        for (int i = 0; i < 4; i++) {
#pragma unroll
            for (int c = 0; c < 4; c++) {
                float vv = pairsum(acc[i][c]);
                int   j  = jbase + k*TJ + tx + 32*c;
                if (vv > tv[i][KTOP-1]) {
                    tv[i][KTOP-1] = vv; ti[i][KTOP-1] = j;
#pragma unroll
                    for (int p = KTOP-1; p > 0; p--) {
                        if (tv[i][p] > tv[i][p-1]) {
                            float fv = tv[i][p]; tv[i][p] = tv[i][p-1]; tv[i][p-1] = fv;
                            int   fi = ti[i][p]; ti[i][p] = ti[i][p-1]; ti[i][p-1] = fi;
                        }
                    }
                }
            }
        }
        __syncthreads();
    }

    // warp merge across 32 lanes -> per-pass top-5 candidates
#pragma unroll
    for (int i = 0; i < 4; i++) {
        int p = 0;
        for (int s = 0; s < KTOP; s++) {
            float v = (p < KTOP) ? tv[i][p] : -INFINITY;
            int   j = (p < KTOP) ? ti[i][p] : 0x7fffffff;
            float bv = v; int bj = j;
#pragma unroll
            for (int off = 16; off; off >>= 1) {
                float ov = __shfl_xor_sync(0xffffffffu, bv, off);
                int   oj = __shfl_xor_sync(0xffffffffu, bj, off);
                if (ov > bv || (ov == bv && oj < bj)) { bv = ov; bj = oj; }
            }
            if (bj == j && bv == v && p < KTOP) p++;
            if (tx == 0) {
                int r = row0 + w*4 + i;
                g_cv[(blockIdx.y*NTOT + r)*KTOP + s] = bv;
                g_cj[(blockIdx.y*NTOT + r)*KTOP + s] = bj;
            }
        }
    }
}

// merge NSPLIT candidate lists per row -> final top-5 indices
__global__ void topk_merge() {
    int r = blockIdx.x * blockDim.x + threadIdx.x;
    if (r >= NTOT) return;
    float v[NSPLIT*KTOP]; int j[NSPLIT*KTOP];
#pragma unroll
    for (int p = 0; p < NSPLIT; p++)
#pragma unroll
        for (int s = 0; s < KTOP; s++) {
            v[p*KTOP+s] = g_cv[(p*NTOT + r)*KTOP + s];
            j[p*KTOP+s] = g_cj[(p*NTOT + r)*KTOP + s];
        }
#pragma unroll
    for (int s = 0; s < KTOP; s++) {
        int b = 0;
#pragma unroll
        for (int t = 1; t < NSPLIT*KTOP; t++)
            if (v[t] > v[b] || (v[t] == v[b] && j[t] < j[b])) b = t;
        g_topk[r*KTOP + s] = j[b];
        v[b] = -INFINITY; j[b] = 0x7fffffff;
    }
}

// ---------------------------------------------------------------------------
// Q/K/V projections for ALL nodes. Y = ego2 @ W^T + b, K=64, f32x2, LDS.128.
__global__ __launch_bounds__(256) void qkv_kernel(
    const float* __restrict__ Wq, const float* __restrict__ bq,
    const float* __restrict__ Wk, const float* __restrict__ bk,
    const float* __restrict__ Wv, const float* __restrict__ bv) {
    __shared__ float Xs[64*RS];
    __shared__ float Ws[64*RS];

    const float *W, *bias; float* Y;
    if (blockIdx.y == 0)      { W = Wq; bias = bq; Y = g_q; }
    else if (blockIdx.y == 1) { W = Wk; bias = bk; Y = g_k; }
    else                      { W = Wv; bias = bv; Y = g_v; }

    int tid  = threadIdx.x;
    int txc  = tid & 15;
    int ty   = tid >> 4;
    int row0 = blockIdx.x * 64;

    for (int idx = tid; idx < 64*16; idx += 256) {
        int r = idx >> 4, q2 = idx & 15;
        *(float4*)&Xs[r*RS + q2*4] = *(const float4*)&g_ego2[(row0 + r)*EDIM + q2*4];
    }

    for (int cc = 0; cc < 4; cc++) {
        __syncthreads();
        for (int idx = tid; idx < 64*16; idx += 256) {
            int c = idx >> 4, q2 = idx & 15;
            *(float4*)&Ws[c*RS + q2*4] = *(const float4*)&W[(cc*64 + c)*EDIM + q2*4];
        }
        __syncthreads();

        ull acc[4][4];
#pragma unroll
        for (int i = 0; i < 4; i++)
#pragma unroll
            for (int c = 0; c < 4; c++) acc[i][c] = 0ull;

#pragma unroll 4
        for (int u = 0; u < 16; u++) {
            float4 a0 = *(const float4*)&Xs[(ty*4 + 0)*RS + u*4];
            float4 a1 = *(const float4*)&Xs[(ty*4 + 1)*RS + u*4];
            float4 a2 = *(const float4*)&Xs[(ty*4 + 2)*RS + u*4];
            float4 a3 = *(const float4*)&Xs[(ty*4 + 3)*RS + u*4];
            float4 b0 = *(const float4*)&Ws[(txc +  0)*RS + u*4];
            float4 b1 = *(const float4*)&Ws[(txc + 16)*RS + u*4];
            float4 b2 = *(const float4*)&Ws[(txc + 32)*RS + u*4];
            float4 b3 = *(const float4*)&Ws[(txc + 48)*RS + u*4];
            const ull* A0 = (const ull*)&a0; const ull* A1 = (const ull*)&a1;
            const ull* A2 = (const ull*)&a2; const ull* A3 = (const ull*)&a3;
            const ull* B0 = (const ull*)&b0; const ull* B1 = (const ull*)&b1;
            const ull* B2 = (const ull*)&b2; const ull* B3 = (const ull*)&b3;
#pragma unroll
            for (int h = 0; h < 2; h++) {
                acc[0][0]=fma2(A0[h],B0[h],acc[0][0]); acc[0][1]=fma2(A0[h],B1[h],acc[0][1]);
                acc[0][2]=fma2(A0[h],B2[h],acc[0][2]); acc[0][3]=fma2(A0[h],B3[h],acc[0][3]);
                acc[1][0]=fma2(A1[h],B0[h],acc[1][0]); acc[1][1]=fma2(A1[h],B1[h],acc[1][1]);
                acc[1][2]=fma2(A1[h],B2[h],acc[1][2]); acc[1][3]=fma2(A1[h],B3[h],acc[1][3]);
                acc[2][0]=fma2(A2[h],B0[h],acc[2][0]); acc[2][1]=fma2(A2[h],B1[h],acc[2][1]);
                acc[2][2]=fma2(A2[h],B2[h],acc[2][2]); acc[2][3]=fma2(A2[h],B3[h],acc[2][3]);
                acc[3][0]=fma2(A3[h],B0[h],acc[3][0]); acc[3][1]=fma2(A3[h],B1[h],acc[3][1]);
                acc[3][2]=fma2(A3[h],B2[h],acc[3][2]); acc[3][3]=fma2(A3[h],B3[h],acc[3][3]);
            }
        }

#pragma unroll
        for (int i = 0; i < 4; i++)
#pragma unroll
            for (int c = 0; c < 4; c++) {
                int col = cc*64 + txc + 16*c;
                Y[(row0 + ty*4 + i)*DQK + col] = pairsum(acc[i][c]) + bias[col];
            }
    }
}

// ---------------------------------------------------------------------------
// Gather K/V via top-k, softmax over 5, weighted V sum. One warp per row.
__global__ __launch_bounds__(256) void attn_kernel(float* __restrict__ out) {
    int gw   = (blockIdx.x * 256 + threadIdx.x) >> 5;
    int lane = threadIdx.x & 31;
    if (gw >= NTOT) return;

    int idx[KTOP];
#pragma unroll
    for (int k = 0; k < KTOP; k++) idx[k] = g_topk[gw*KTOP + k];

    const float4* q4 = (const float4*)(g_q + gw*DQK);
    float4 qa = q4[lane*2], qb = q4[lane*2 + 1];

    float s[KTOP];
#pragma unroll
    for (int k = 0; k < KTOP; k++) {
        const float4* k4 = (const float4*)(g_k + idx[k]*DQK);
        float4 ka = k4[lane*2], kb = k4[lane*2 + 1];
        float p = qa.x*ka.x + qa.y*ka.y + qa.z*ka.z + qa.w*ka.w
                + qb.x*kb.x + qb.y*kb.y + qb.z*kb.z + qb.w*kb.w;
#pragma unroll
        for (int off = 16; off; off >>= 1) p += __shfl_xor_sync(0xffffffffu, p, off);
        s[k] = p * (1.0f / 16.0f);
    }

    float m = s[0];
#pragma unroll
    for (int k = 1; k < KTOP; k++) m = fmaxf(m, s[k]);
    float esum = 0.f;
#pragma unroll
    for (int k = 0; k < KTOP; k++) { s[k] = expf(s[k] - m); esum += s[k]; }
    float inv = 1.f / esum;

    float4 oa = make_float4(0.f,0.f,0.f,0.f), ob = make_float4(0.f,0.f,0.f,0.f);
#pragma unroll
    for (int k = 0; k < KTOP; k++) {
        const float4* v4 = (const float4*)(g_v + idx[k]*DQK);
        float4 va = v4[lane*2], vb = v4[lane*2 + 1];
        float a = s[k] * inv;
        oa.x += a*va.x; oa.y += a*va.y; oa.z += a*va.z; oa.w += a*va.w;
        ob.x += a*vb.x; ob.y += a*vb.y; ob.z += a*vb.z; ob.w += a*vb.w;
    }
    float4* o4 = (float4*)(out + gw*DQK);
    o4[lane*2] = oa; o4[lane*2 + 1] = ob;
}

// ---------------------------------------------------------------------------
extern "C" void kernel_launch(void* const* d_in, const int* in_sizes, int n_in,
                              void* d_out, int out_size) {
    const float* ue = (const float*)d_in[0];
    const float* ie = (const float*)d_in[1];
    const int*   nr = (const int*)d_in[2];
    const int*   nc = (const int*)d_in[3];
    const float* nv = (const float*)d_in[4];
    const int*   ar = (const int*)d_in[5];
    const int*   ac = (const int*)d_in[6];
    const float* av = (const float*)d_in[7];
    const float* Wq = (const float*)d_in[8];
    const float* bq = (const float*)d_in[9];
    const float* Wk = (const float*)d_in[10];
    const float* bk = (const float*)d_in[11];
    const float* Wv = (const float*)d_in[12];
    const float* bv = (const float*)d_in[13];
    float* out = (float*)d_out;

    int nnz = in_sizes[2];
    int ew_blocks   = (NTOT*EDIM + 255) / 256;
    int spmm_blocks = (nnz*16 + 255) / 256;
    int es_bytes    = 2 * TJ * RS * sizeof(float);

    static int smem_set = 0;
    if (!smem_set) {
        cudaFuncSetAttribute(topk_pass, cudaFuncAttributeMaxDynamicSharedMemorySize, es_bytes);
        smem_set = 1;
    }

    float *ego0, *ego1, *ego2, *B;
    cudaGetSymbolAddress((void**)&ego0, g_ego0);
    cudaGetSymbolAddress((void**)&ego1, g_ego1);
    cudaGetSymbolAddress((void**)&ego2, g_ego2);
    cudaGetSymbolAddress((void**)&B,    g_B);

    init_kernel<<<ew_blocks, 256>>>(ue, ie);                                // 1
    spmm_atomic<<<spmm_blocks, 256>>>(nr, nc, nv, ego0, ego1, 1.0f, nnz);   // 2: ego1=An@ego0
    spmm_atomic<<<spmm_blocks, 256>>>(nr, nc, nv, ego1, ego2, 1.0f, nnz);   // 3: ego2=An@ego1
    copyB_kernel<<<ew_blocks, 256>>>();                                     // 4: B=ego2
    spmm_atomic<<<spmm_blocks, 256>>>(ar, ac, av, ego2, B, 0.5f, nnz);      // 5: B+=0.5*A@ego2
    topk_pass<<<dim3(NTOT/32, NSPLIT), 256, es_bytes>>>();                  // 6 (profiled)
    topk_merge<<<(NTOT + 255)/256, 256>>>();                                // 7
    qkv_kernel<<<dim3(NTOT/64, 3), 256>>>(Wq, bq, Wk, bk, Wv, bv);          // 8
    attn_kernel<<<(NTOT*32 + 255)/256, 256>>>(out + NTOT*EDIM);             // 9
    mean_kernel<<<ew_blocks, 256>>>(out);                                   // 10
}

// round 4
// speedup vs baseline: 1.6463x; 1.0806x over previous
#include <cuda_runtime.h>
#include <math.h>

#define NU   2560
#define NI   3584
#define NTOT 6144
#define EDIM 64
#define DQK  256
#define KTOP 5
#define RS   68          // smem row stride (floats); 16B-aligned rows for cp.async
#define NSPLIT 3
#define TJ   128

// ---- device scratch ----
__device__ float g_ego0[NTOT*EDIM];
__device__ float g_ego1[NTOT*EDIM];
__device__ float g_ego2[NTOT*EDIM];
__device__ float g_B   [NTOT*EDIM];     // holds 0.5 * A @ ego2 (zero-initialized)
__device__ float g_cv[NSPLIT*NTOT*KTOP];
__device__ int   g_cj[NSPLIT*NTOT*KTOP];
__device__ float g_q [NTOT*DQK];
__device__ float g_k [NTOT*DQK];
__device__ float g_v [NTOT*DQK];

typedef unsigned long long ull;

__device__ __forceinline__ ull fma2(ull a, ull b, ull c) {
    ull d;
    asm("fma.rn.f32x2 %0, %1, %2, %3;" : "=l"(d) : "l"(a), "l"(b), "l"(c));
    return d;
}
__device__ __forceinline__ float pairsum(ull p) {
    return __uint_as_float((unsigned)p) + __uint_as_float((unsigned)(p >> 32));
}
__device__ __forceinline__ void cp16(void* dst, const void* src) {
    unsigned s = (unsigned)__cvta_generic_to_shared(dst);
    asm volatile("cp.async.cg.shared.global [%0], [%1], 16;" :: "r"(s), "l"(src) : "memory");
}

// ---------------------------------------------------------------------------
__global__ void init_kernel(const float* __restrict__ ue, const float* __restrict__ ie) {
    int i = blockIdx.x * blockDim.x + threadIdx.x;
    if (i < NTOT*EDIM) {
        g_ego0[i] = (i < NU*EDIM) ? ue[i] : ie[i - NU*EDIM];
        g_ego1[i] = 0.f;
        g_ego2[i] = 0.f;
        g_B[i]    = 0.f;
    }
}

// dst[row] += scale * val * src[col]  — 16 threads/nnz, red.v4
__global__ void spmm_atomic(const int* __restrict__ rows, const int* __restrict__ cols,
                            const float* __restrict__ vals,
                            const float* __restrict__ src, float* __restrict__ dst,
                            float scale, int nnz) {
    int t = blockIdx.x * blockDim.x + threadIdx.x;
    int nz = t >> 4;
    if (nz >= nnz) return;
    int e = (t & 15) * 4;
    float v = vals[nz] * scale;
    float4 s = *(const float4*)&src[cols[nz]*EDIM + e];
    float* d = &dst[rows[nz]*EDIM + e];
    asm volatile("red.global.add.v4.f32 [%0], {%1,%2,%3,%4};"
                 :: "l"(d), "f"(v*s.x), "f"(v*s.y), "f"(v*s.z), "f"(v*s.w) : "memory");
}

__global__ void mean_kernel(float* __restrict__ out) {
    int i = blockIdx.x * blockDim.x + threadIdx.x;
    if (i < NTOT*EDIM) out[i] = 0.5f * (g_ego0[i] + g_ego1[i]);
}

// ---------------------------------------------------------------------------
// Fused sim GEMM + per-row top-5 over one j-third. 32 rows/block, TJ=128,
// per-thread 4x4, A-tile = ego2 + g_B staged to smem, double-buffered Es.
__global__ __launch_bounds__(256, 2) void topk_pass() {
    __shared__ float Bs[32*RS];
    extern __shared__ float Es[];       // 2 * TJ * RS floats

    int tid  = threadIdx.x;
    int tx   = tid & 31;
    int w    = tid >> 5;
    int row0 = blockIdx.x * 32;
    int jbase = blockIdx.y * (NTOT / NSPLIT);
    const int NCH = (NTOT / NSPLIT) / TJ;   // 16

    for (int idx = tid; idx < 32*32; idx += 256) {       // float2 granularity
        int r = idx >> 5, e2 = idx & 31;
        float2 a = *(const float2*)&g_ego2[(row0 + r)*EDIM + 2*e2];
        float2 b = *(const float2*)&g_B   [(row0 + r)*EDIM + 2*e2];
        a.x += b.x; a.y += b.y;
        *(float2*)&Bs[r*RS + 2*e2] = a;
    }

    // prefetch chunk 0
    for (int idx = tid; idx < TJ*16; idx += 256) {
        int c = idx >> 4, q2 = idx & 15;
        cp16(&Es[c*RS + q2*4], &g_ego2[(jbase + c)*EDIM + q2*4]);
    }
    asm volatile("cp.async.commit_group;");

    float tv[4][KTOP];
    int   ti[4][KTOP];
#pragma unroll
    for (int i = 0; i < 4; i++)
#pragma unroll
        for (int s = 0; s < KTOP; s++) { tv[i][s] = -INFINITY; ti[i][s] = 0x7fffffff; }

    for (int k = 0; k < NCH; k++) {
        int cur = (k & 1) * TJ * RS;
        if (k + 1 < NCH) {
            int nxt = ((k + 1) & 1) * TJ * RS;
            int jn = jbase + (k + 1) * TJ;
            for (int idx = tid; idx < TJ*16; idx += 256) {
                int c = idx >> 4, q2 = idx & 15;
                cp16(&Es[nxt + c*RS + q2*4], &g_ego2[(jn + c)*EDIM + q2*4]);
            }
            asm volatile("cp.async.commit_group;");
            asm volatile("cp.async.wait_group 1;");
        } else {
            asm volatile("cp.async.wait_group 0;");
        }
        __syncthreads();

        ull acc[4][4];
#pragma unroll
        for (int i = 0; i < 4; i++)
#pragma unroll
            for (int c = 0; c < 4; c++) acc[i][c] = 0ull;

#pragma unroll 4
        for (int u = 0; u < 16; u++) {      // 4 K-floats per step
            float4 a0 = *(const float4*)&Bs[(w*4 + 0)*RS + u*4];
            float4 a1 = *(const float4*)&Bs[(w*4 + 1)*RS + u*4];
            float4 a2 = *(const float4*)&Bs[(w*4 + 2)*RS + u*4];
            float4 a3 = *(const float4*)&Bs[(w*4 + 3)*RS + u*4];
            float4 b0 = *(const float4*)&Es[cur + (tx +  0)*RS + u*4];
            float4 b1 = *(const float4*)&Es[cur + (tx + 32)*RS + u*4];
            float4 b2 = *(const float4*)&Es[cur + (tx + 64)*RS + u*4];
            float4 b3 = *(const float4*)&Es[cur + (tx + 96)*RS + u*4];
            const ull* A0 = (const ull*)&a0; const ull* A1 = (const ull*)&a1;
            const ull* A2 = (const ull*)&a2; const ull* A3 = (const ull*)&a3;
            const ull* B0 = (const ull*)&b0; const ull* B1 = (const ull*)&b1;
            const ull* B2 = (const ull*)&b2; const ull* B3 = (const ull*)&b3;
#pragma unroll
            for (int h = 0; h < 2; h++) {
                acc[0][0]=fma2(A0[h],B0[h],acc[0][0]); acc[0][1]=fma2(A0[h],B1[h],acc[0][1]);
                acc[0][2]=fma2(A0[h],B2[h],acc[0][2]); acc[0][3]=fma2(A0[h],B3[h],acc[0][3]);
                acc[1][0]=fma2(A1[h],B0[h],acc[1][0]); acc[1][1]=fma2(A1[h],B1[h],acc[1][1]);
                acc[1][2]=fma2(A1[h],B2[h],acc[1][2]); acc[1][3]=fma2(A1[h],B3[h],acc[1][3]);
                acc[2][0]=fma2(A2[h],B0[h],acc[2][0]); acc[2][1]=fma2(A2[h],B1[h],acc[2][1]);
                acc[2][2]=fma2(A2[h],B2[h],acc[2][2]); acc[2][3]=fma2(A2[h],B3[h],acc[2][3]);
                acc[3][0]=fma2(A3[h],B0[h],acc[3][0]); acc[3][1]=fma2(A3[h],B1[h],acc[3][1]);
                acc[3][2]=fma2(A3[h],B2[h],acc[3][2]); acc[3][3]=fma2(A3[h],B3[h],acc[3][3]);
            }
        }

        // top-5 insert; j ascending -> strict > keeps smallest index on ties
#pragma unroll
        for (int i = 0; i < 4; i++) {
#pragma unroll
            for (int c = 0; c < 4; c++) {
                float vv = pairsum(acc[i][c]);
                int   j  = jbase + k*TJ + tx + 32*c;
                if (vv > tv[i][KTOP-1]) {
                    tv[i][KTOP-1] = vv; ti[i][KTOP-1] = j;
#pragma unroll
                    for (int p = KTOP-1; p > 0; p--) {
                        if (tv[i][p] > tv[i][p-1]) {
                            float fv = tv[i][p]; tv[i][p] = tv[i][p-1]; tv[i][p-1] = fv;
                            int   fi = ti[i][p]; ti[i][p] = ti[i][p-1]; ti[i][p-1] = fi;
                        }
                    }
                }
            }
        }
        __syncthreads();
    }

    // warp merge across 32 lanes -> per-pass top-5 candidates
#pragma unroll
    for (int i = 0; i < 4; i++) {
        int p = 0;
        for (int s = 0; s < KTOP; s++) {
            float v = (p < KTOP) ? tv[i][p] : -INFINITY;
            int   j = (p < KTOP) ? ti[i][p] : 0x7fffffff;
            float bv = v; int bj = j;
#pragma unroll
            for (int off = 16; off; off >>= 1) {
                float ov = __shfl_xor_sync(0xffffffffu, bv, off);
                int   oj = __shfl_xor_sync(0xffffffffu, bj, off);
                if (ov > bv || (ov == bv && oj < bj)) { bv = ov; bj = oj; }
            }
            if (bj == j && bv == v && p < KTOP) p++;
            if (tx == 0) {
                int r = row0 + w*4 + i;
                g_cv[(blockIdx.y*NTOT + r)*KTOP + s] = bv;
                g_cj[(blockIdx.y*NTOT + r)*KTOP + s] = bj;
            }
        }
    }
}

// ---------------------------------------------------------------------------
// Q/K/V projections for ALL nodes. Y = ego2 @ W^T + b, K=64, f32x2, LDS.128.
__global__ __launch_bounds__(256) void qkv_kernel(
    const float* __restrict__ Wq, const float* __restrict__ bq,
    const float* __restrict__ Wk, const float* __restrict__ bk,
    const float* __restrict__ Wv, const float* __restrict__ bv) {
    __shared__ float Xs[64*RS];
    __shared__ float Ws[64*RS];

    const float *W, *bias; float* Y;
    if (blockIdx.y == 0)      { W = Wq; bias = bq; Y = g_q; }
    else if (blockIdx.y == 1) { W = Wk; bias = bk; Y = g_k; }
    else                      { W = Wv; bias = bv; Y = g_v; }

    int tid  = threadIdx.x;
    int txc  = tid & 15;
    int ty   = tid >> 4;
    int row0 = blockIdx.x * 64;

    for (int idx = tid; idx < 64*16; idx += 256) {
        int r = idx >> 4, q2 = idx & 15;
        *(float4*)&Xs[r*RS + q2*4] = *(const float4*)&g_ego2[(row0 + r)*EDIM + q2*4];
    }

    for (int cc = 0; cc < 4; cc++) {
        __syncthreads();
        for (int idx = tid; idx < 64*16; idx += 256) {
            int c = idx >> 4, q2 = idx & 15;
            *(float4*)&Ws[c*RS + q2*4] = *(const float4*)&W[(cc*64 + c)*EDIM + q2*4];
        }
        __syncthreads();

        ull acc[4][4];
#pragma unroll
        for (int i = 0; i < 4; i++)
#pragma unroll
            for (int c = 0; c < 4; c++) acc[i][c] = 0ull;

#pragma unroll 4
        for (int u = 0; u < 16; u++) {
            float4 a0 = *(const float4*)&Xs[(ty*4 + 0)*RS + u*4];
            float4 a1 = *(const float4*)&Xs[(ty*4 + 1)*RS + u*4];
            float4 a2 = *(const float4*)&Xs[(ty*4 + 2)*RS + u*4];
            float4 a3 = *(const float4*)&Xs[(ty*4 + 3)*RS + u*4];
            float4 b0 = *(const float4*)&Ws[(txc +  0)*RS + u*4];
            float4 b1 = *(const float4*)&Ws[(txc + 16)*RS + u*4];
            float4 b2 = *(const float4*)&Ws[(txc + 32)*RS + u*4];
            float4 b3 = *(const float4*)&Ws[(txc + 48)*RS + u*4];
            const ull* A0 = (const ull*)&a0; const ull* A1 = (const ull*)&a1;
            const ull* A2 = (const ull*)&a2; const ull* A3 = (const ull*)&a3;
            const ull* B0 = (const ull*)&b0; const ull* B1 = (const ull*)&b1;
            const ull* B2 = (const ull*)&b2; const ull* B3 = (const ull*)&b3;
#pragma unroll
            for (int h = 0; h < 2; h++) {
                acc[0][0]=fma2(A0[h],B0[h],acc[0][0]); acc[0][1]=fma2(A0[h],B1[h],acc[0][1]);
                acc[0][2]=fma2(A0[h],B2[h],acc[0][2]); acc[0][3]=fma2(A0[h],B3[h],acc[0][3]);
                acc[1][0]=fma2(A1[h],B0[h],acc[1][0]); acc[1][1]=fma2(A1[h],B1[h],acc[1][1]);
                acc[1][2]=fma2(A1[h],B2[h],acc[1][2]); acc[1][3]=fma2(A1[h],B3[h],acc[1][3]);
                acc[2][0]=fma2(A2[h],B0[h],acc[2][0]); acc[2][1]=fma2(A2[h],B1[h],acc[2][1]);
                acc[2][2]=fma2(A2[h],B2[h],acc[2][2]); acc[2][3]=fma2(A2[h],B3[h],acc[2][3]);
                acc[3][0]=fma2(A3[h],B0[h],acc[3][0]); acc[3][1]=fma2(A3[h],B1[h],acc[3][1]);
                acc[3][2]=fma2(A3[h],B2[h],acc[3][2]); acc[3][3]=fma2(A3[h],B3[h],acc[3][3]);
            }
        }

#pragma unroll
        for (int i = 0; i < 4; i++)
#pragma unroll
            for (int c = 0; c < 4; c++) {
                int col = cc*64 + txc + 16*c;
                Y[(row0 + ty*4 + i)*DQK + col] = pairsum(acc[i][c]) + bias[col];
            }
    }
}

// ---------------------------------------------------------------------------
// Inline candidate merge + gather K/V + softmax + weighted V sum. Warp/row.
__global__ __launch_bounds__(256) void attn_kernel(float* __restrict__ out) {
    int gw   = (blockIdx.x * 256 + threadIdx.x) >> 5;
    int lane = threadIdx.x & 31;
    if (gw >= NTOT) return;

    // merge NSPLIT candidate lists (value desc, index asc), replicated per lane
    float cv[NSPLIT*KTOP]; int cj[NSPLIT*KTOP];
#pragma unroll
    for (int p = 0; p < NSPLIT; p++)
#pragma unroll
        for (int s = 0; s < KTOP; s++) {
            cv[p*KTOP+s] = g_cv[(p*NTOT + gw)*KTOP + s];
            cj[p*KTOP+s] = g_cj[(p*NTOT + gw)*KTOP + s];
        }
    int idx[KTOP];
#pragma unroll
    for (int s = 0; s < KTOP; s++) {
        int b = 0;
#pragma unroll
        for (int t = 1; t < NSPLIT*KTOP; t++)
            if (cv[t] > cv[b] || (cv[t] == cv[b] && cj[t] < cj[b])) b = t;
        idx[s] = cj[b];
        cv[b] = -INFINITY; cj[b] = 0x7fffffff;
    }

    const float4* q4 = (const float4*)(g_q + gw*DQK);
    float4 qa = q4[lane*2], qb = q4[lane*2 + 1];

    float s[KTOP];
#pragma unroll
    for (int k = 0; k < KTOP; k++) {
        const float4* k4 = (const float4*)(g_k + idx[k]*DQK);
        float4 ka = k4[lane*2], kb = k4[lane*2 + 1];
        float p = qa.x*ka.x + qa.y*ka.y + qa.z*ka.z + qa.w*ka.w
                + qb.x*kb.x + qb.y*kb.y + qb.z*kb.z + qb.w*kb.w;
#pragma unroll
        for (int off = 16; off; off >>= 1) p += __shfl_xor_sync(0xffffffffu, p, off);
        s[k] = p * (1.0f / 16.0f);
    }

    float m = s[0];
#pragma unroll
    for (int k = 1; k < KTOP; k++) m = fmaxf(m, s[k]);
    float esum = 0.f;
#pragma unroll
    for (int k = 0; k < KTOP; k++) { s[k] = expf(s[k] - m); esum += s[k]; }
    float inv = 1.f / esum;

    float4 oa = make_float4(0.f,0.f,0.f,0.f), ob = make_float4(0.f,0.f,0.f,0.f);
#pragma unroll
    for (int k = 0; k < KTOP; k++) {
        const float4* v4 = (const float4*)(g_v + idx[k]*DQK);
        float4 va = v4[lane*2], vb = v4[lane*2 + 1];
        float a = s[k] * inv;
        oa.x += a*va.x; oa.y += a*va.y; oa.z += a*va.z; oa.w += a*va.w;
        ob.x += a*vb.x; ob.y += a*vb.y; ob.z += a*vb.z; ob.w += a*vb.w;
    }
    float4* o4 = (float4*)(out + gw*DQK);
    o4[lane*2] = oa; o4[lane*2 + 1] = ob;
}

// ---------------------------------------------------------------------------
extern "C" void kernel_launch(void* const* d_in, const int* in_sizes, int n_in,
                              void* d_out, int out_size) {
    const float* ue = (const float*)d_in[0];
    const float* ie = (const float*)d_in[1];
    const int*   nr = (const int*)d_in[2];
    const int*   nc = (const int*)d_in[3];
    const float* nv = (const float*)d_in[4];
    const int*   ar = (const int*)d_in[5];
    const int*   ac = (const int*)d_in[6];
    const float* av = (const float*)d_in[7];
    const float* Wq = (const float*)d_in[8];
    const float* bq = (const float*)d_in[9];
    const float* Wk = (const float*)d_in[10];
    const float* bk = (const float*)d_in[11];
    const float* Wv = (const float*)d_in[12];
    const float* bv = (const float*)d_in[13];
    float* out = (float*)d_out;

    int nnz = in_sizes[2];
    int ew_blocks   = (NTOT*EDIM + 255) / 256;
    int spmm_blocks = (nnz*16 + 255) / 256;
    int es_bytes    = 2 * TJ * RS * sizeof(float);

    static int smem_set = 0;
    if (!smem_set) {
        cudaFuncSetAttribute(topk_pass, cudaFuncAttributeMaxDynamicSharedMemorySize, es_bytes);
        smem_set = 1;
    }

    float *ego0, *ego1, *ego2, *B;
    cudaGetSymbolAddress((void**)&ego0, g_ego0);
    cudaGetSymbolAddress((void**)&ego1, g_ego1);
    cudaGetSymbolAddress((void**)&ego2, g_ego2);
    cudaGetSymbolAddress((void**)&B,    g_B);

    init_kernel<<<ew_blocks, 256>>>(ue, ie);                                // #1
    spmm_atomic<<<spmm_blocks, 256>>>(nr, nc, nv, ego0, ego1, 1.0f, nnz);   // #2 ego1=An@ego0
    spmm_atomic<<<spmm_blocks, 256>>>(nr, nc, nv, ego1, ego2, 1.0f, nnz);   // #3 ego2=An@ego1
    qkv_kernel<<<dim3(NTOT/64, 3), 256>>>(Wq, bq, Wk, bk, Wv, bv);          // #4  <-- PROFILED
    spmm_atomic<<<spmm_blocks, 256>>>(ar, ac, av, ego2, B, 0.5f, nnz);      // #5 B=0.5*A@ego2
    topk_pass<<<dim3(NTOT/32, NSPLIT), 256, es_bytes>>>();                  // #6 sim + top5
    attn_kernel<<<(NTOT*32 + 255)/256, 256>>>(out + NTOT*EDIM);             // #7 merge+attn
    mean_kernel<<<ew_blocks, 256>>>(out);                                   // #8
}

// round 5
// speedup vs baseline: 2.7238x; 1.6545x over previous
#include <cuda_runtime.h>
#include <math.h>

#define NU   2560
#define NI   3584
#define NTOT 6144
#define EDIM 64
#define DQK  256
#define KTOP 5
#define RS   68          // smem row stride (floats); 16B-aligned rows for cp.async
#define NSPLIT 3
#define TJ   128

// ---- device scratch ----
__device__ float g_ego0[NTOT*EDIM];
__device__ float g_ego1[NTOT*EDIM];
__device__ float g_ego2[NTOT*EDIM];
__device__ float g_B   [NTOT*EDIM];     // holds 0.5 * A @ ego2 (zero-initialized)
__device__ float g_cv[NSPLIT*NTOT*KTOP];
__device__ int   g_cj[NSPLIT*NTOT*KTOP];
__device__ float g_q [NTOT*DQK];
__device__ float g_k [NTOT*DQK];
__device__ float g_v [NTOT*DQK];

typedef unsigned long long ull;

__device__ __forceinline__ ull fma2(ull a, ull b, ull c) {
    ull d;
    asm("fma.rn.f32x2 %0, %1, %2, %3;" : "=l"(d) : "l"(a), "l"(b), "l"(c));
    return d;
}
__device__ __forceinline__ float pairsum(ull p) {
    return __uint_as_float((unsigned)p) + __uint_as_float((unsigned)(p >> 32));
}
__device__ __forceinline__ void cp16(void* dst, const void* src) {
    unsigned s = (unsigned)__cvta_generic_to_shared(dst);
    asm volatile("cp.async.cg.shared.global [%0], [%1], 16;" :: "r"(s), "l"(src) : "memory");
}

// ---------------------------------------------------------------------------
__global__ void init_kernel(const float* __restrict__ ue, const float* __restrict__ ie) {
    int i = blockIdx.x * blockDim.x + threadIdx.x;
    if (i < NTOT*EDIM) {
        g_ego0[i] = (i < NU*EDIM) ? ue[i] : ie[i - NU*EDIM];
        g_ego1[i] = 0.f;
        g_ego2[i] = 0.f;
        g_B[i]    = 0.f;
    }
}

// dst[row] += scale * val * src[col]  — 16 threads/nnz, red.v4
__global__ void spmm_atomic(const int* __restrict__ rows, const int* __restrict__ cols,
                            const float* __restrict__ vals,
                            const float* __restrict__ src, float* __restrict__ dst,
                            float scale, int nnz) {
    int t = blockIdx.x * blockDim.x + threadIdx.x;
    int nz = t >> 4;
    if (nz >= nnz) return;
    int e = (t & 15) * 4;
    float v = vals[nz] * scale;
    float4 s = *(const float4*)&src[cols[nz]*EDIM + e];
    float* d = &dst[rows[nz]*EDIM + e];
    asm volatile("red.global.add.v4.f32 [%0], {%1,%2,%3,%4};"
                 :: "l"(d), "f"(v*s.x), "f"(v*s.y), "f"(v*s.z), "f"(v*s.w) : "memory");
}

__global__ void mean_kernel(float* __restrict__ out) {
    int i = blockIdx.x * blockDim.x + threadIdx.x;
    if (i < NTOT*EDIM) out[i] = 0.5f * (g_ego0[i] + g_ego1[i]);
}

// ---------------------------------------------------------------------------
// Fused sim GEMM + per-row top-5 over one j-third. 32 rows/block, TJ=128,
// per-thread 4x4, A-tile = ego2 + g_B staged to smem, double-buffered Es.
// ALL per-thread arrays statically indexed (registers, no local-mem demotion).
__global__ __launch_bounds__(256, 2) void topk_pass() {
    __shared__ float Bs[32*RS];
    extern __shared__ float Es[];       // 2 * TJ * RS floats

    int tid  = threadIdx.x;
    int tx   = tid & 31;
    int w    = tid >> 5;
    int row0 = blockIdx.x * 32;
    int jbase = blockIdx.y * (NTOT / NSPLIT);
    const int NCH = (NTOT / NSPLIT) / TJ;   // 16

    for (int idx = tid; idx < 32*32; idx += 256) {       // float2 granularity
        int r = idx >> 5, e2 = idx & 31;
        float2 a = *(const float2*)&g_ego2[(row0 + r)*EDIM + 2*e2];
        float2 b = *(const float2*)&g_B   [(row0 + r)*EDIM + 2*e2];
        a.x += b.x; a.y += b.y;
        *(float2*)&Bs[r*RS + 2*e2] = a;
    }

    // prefetch chunk 0
    for (int idx = tid; idx < TJ*16; idx += 256) {
        int c = idx >> 4, q2 = idx & 15;
        cp16(&Es[c*RS + q2*4], &g_ego2[(jbase + c)*EDIM + q2*4]);
    }
    asm volatile("cp.async.commit_group;");

    float tv[4][KTOP];
    int   ti[4][KTOP];
#pragma unroll
    for (int i = 0; i < 4; i++)
#pragma unroll
        for (int s = 0; s < KTOP; s++) { tv[i][s] = -INFINITY; ti[i][s] = 0x7fffffff; }

    for (int k = 0; k < NCH; k++) {
        int cur = (k & 1) * TJ * RS;
        if (k + 1 < NCH) {
            int nxt = ((k + 1) & 1) * TJ * RS;
            int jn = jbase + (k + 1) * TJ;
            for (int idx = tid; idx < TJ*16; idx += 256) {
                int c = idx >> 4, q2 = idx & 15;
                cp16(&Es[nxt + c*RS + q2*4], &g_ego2[(jn + c)*EDIM + q2*4]);
            }
            asm volatile("cp.async.commit_group;");
            asm volatile("cp.async.wait_group 1;");
        } else {
            asm volatile("cp.async.wait_group 0;");
        }
        __syncthreads();

        ull acc[4][4];
#pragma unroll
        for (int i = 0; i < 4; i++)
#pragma unroll
            for (int c = 0; c < 4; c++) acc[i][c] = 0ull;

#pragma unroll 4
        for (int u = 0; u < 16; u++) {      // 4 K-floats per step
            float4 a0 = *(const float4*)&Bs[(w*4 + 0)*RS + u*4];
            float4 a1 = *(const float4*)&Bs[(w*4 + 1)*RS + u*4];
            float4 a2 = *(const float4*)&Bs[(w*4 + 2)*RS + u*4];
            float4 a3 = *(const float4*)&Bs[(w*4 + 3)*RS + u*4];
            float4 b0 = *(const float4*)&Es[cur + (tx +  0)*RS + u*4];
            float4 b1 = *(const float4*)&Es[cur + (tx + 32)*RS + u*4];
            float4 b2 = *(const float4*)&Es[cur + (tx + 64)*RS + u*4];
            float4 b3 = *(const float4*)&Es[cur + (tx + 96)*RS + u*4];
            const ull* A0 = (const ull*)&a0; const ull* A1 = (const ull*)&a1;
            const ull* A2 = (const ull*)&a2; const ull* A3 = (const ull*)&a3;
            const ull* B0 = (const ull*)&b0; const ull* B1 = (const ull*)&b1;
            const ull* B2 = (const ull*)&b2; const ull* B3 = (const ull*)&b3;
#pragma unroll
            for (int h = 0; h < 2; h++) {
                acc[0][0]=fma2(A0[h],B0[h],acc[0][0]); acc[0][1]=fma2(A0[h],B1[h],acc[0][1]);
                acc[0][2]=fma2(A0[h],B2[h],acc[0][2]); acc[0][3]=fma2(A0[h],B3[h],acc[0][3]);
                acc[1][0]=fma2(A1[h],B0[h],acc[1][0]); acc[1][1]=fma2(A1[h],B1[h],acc[1][1]);
                acc[1][2]=fma2(A1[h],B2[h],acc[1][2]); acc[1][3]=fma2(A1[h],B3[h],acc[1][3]);
                acc[2][0]=fma2(A2[h],B0[h],acc[2][0]); acc[2][1]=fma2(A2[h],B1[h],acc[2][1]);
                acc[2][2]=fma2(A2[h],B2[h],acc[2][2]); acc[2][3]=fma2(A2[h],B3[h],acc[2][3]);
                acc[3][0]=fma2(A3[h],B0[h],acc[3][0]); acc[3][1]=fma2(A3[h],B1[h],acc[3][1]);
                acc[3][2]=fma2(A3[h],B2[h],acc[3][2]); acc[3][3]=fma2(A3[h],B3[h],acc[3][3]);
            }
        }

        // top-5 insert; ascending j + strict > keeps smallest index on ties.
        // Chunk-level prune: skip the 4-candidate insert if none can enter.
#pragma unroll
        for (int i = 0; i < 4; i++) {
            float v0 = pairsum(acc[i][0]);
            float v1 = pairsum(acc[i][1]);
            float v2 = pairsum(acc[i][2]);
            float v3 = pairsum(acc[i][3]);
            float m4 = fmaxf(fmaxf(v0, v1), fmaxf(v2, v3));
            if (m4 > tv[i][KTOP-1]) {
#pragma unroll
                for (int c = 0; c < 4; c++) {
                    float vv = (c == 0) ? v0 : (c == 1) ? v1 : (c == 2) ? v2 : v3;
                    int   j  = jbase + k*TJ + tx + 32*c;
                    if (vv > tv[i][KTOP-1]) {
                        tv[i][KTOP-1] = vv; ti[i][KTOP-1] = j;
#pragma unroll
                        for (int p = KTOP-1; p > 0; p--) {
                            if (tv[i][p] > tv[i][p-1]) {
                                float fv = tv[i][p]; tv[i][p] = tv[i][p-1]; tv[i][p-1] = fv;
                                int   fi = ti[i][p]; ti[i][p] = ti[i][p-1]; ti[i][p-1] = fi;
                            }
                        }
                    }
                }
            }
        }
        __syncthreads();
    }

    // warp merge across 32 lanes — STATIC indexing only: warp-argmax of each
    // lane's head; the winning lane pops via an unrolled shift-down.
#pragma unroll
    for (int i = 0; i < 4; i++) {
#pragma unroll
        for (int s = 0; s < KTOP; s++) {
            float v = tv[i][0];
            int   j = ti[i][0];
            float bv = v; int bj = j;
#pragma unroll
            for (int off = 16; off; off >>= 1) {
                float ov = __shfl_xor_sync(0xffffffffu, bv, off);
                int   oj = __shfl_xor_sync(0xffffffffu, bj, off);
                if (ov > bv || (ov == bv && oj < bj)) { bv = ov; bj = oj; }
            }
            if (bv == v && bj == j) {   // this lane's head won (j unique per lane)
#pragma unroll
                for (int p = 0; p < KTOP-1; p++) {
                    tv[i][p] = tv[i][p+1]; ti[i][p] = ti[i][p+1];
                }
                tv[i][KTOP-1] = -INFINITY; ti[i][KTOP-1] = 0x7fffffff;
            }
            if (tx == 0) {
                int r = row0 + w*4 + i;
                g_cv[(blockIdx.y*NTOT + r)*KTOP + s] = bv;
                g_cj[(blockIdx.y*NTOT + r)*KTOP + s] = bj;
            }
        }
    }
}

// ---------------------------------------------------------------------------
// Q/K/V projections for ALL nodes. Y = ego2 @ W^T + b, K=64, f32x2, LDS.128.
__global__ __launch_bounds__(256) void qkv_kernel(
    const float* __restrict__ Wq, const float* __restrict__ bq,
    const float* __restrict__ Wk, const float* __restrict__ bk,
    const float* __restrict__ Wv, const float* __restrict__ bv) {
    __shared__ float Xs[64*RS];
    __shared__ float Ws[64*RS];

    const float *W, *bias; float* Y;
    if (blockIdx.y == 0)      { W = Wq; bias = bq; Y = g_q; }
    else if (blockIdx.y == 1) { W = Wk; bias = bk; Y = g_k; }
    else                      { W = Wv; bias = bv; Y = g_v; }

    int tid  = threadIdx.x;
    int txc  = tid & 15;
    int ty   = tid >> 4;
    int row0 = blockIdx.x * 64;

    for (int idx = tid; idx < 64*16; idx += 256) {
        int r = idx >> 4, q2 = idx & 15;
        *(float4*)&Xs[r*RS + q2*4] = *(const float4*)&g_ego2[(row0 + r)*EDIM + q2*4];
    }

    for (int cc = 0; cc < 4; cc++) {
        __syncthreads();
        for (int idx = tid; idx < 64*16; idx += 256) {
            int c = idx >> 4, q2 = idx & 15;
            *(float4*)&Ws[c*RS + q2*4] = *(const float4*)&W[(cc*64 + c)*EDIM + q2*4];
        }
        __syncthreads();

        ull acc[4][4];
#pragma unroll
        for (int i = 0; i < 4; i++)
#pragma unroll
            for (int c = 0; c < 4; c++) acc[i][c] = 0ull;

#pragma unroll 4
        for (int u = 0; u < 16; u++) {
            float4 a0 = *(const float4*)&Xs[(ty*4 + 0)*RS + u*4];
            float4 a1 = *(const float4*)&Xs[(ty*4 + 1)*RS + u*4];
            float4 a2 = *(const float4*)&Xs[(ty*4 + 2)*RS + u*4];
            float4 a3 = *(const float4*)&Xs[(ty*4 + 3)*RS + u*4];
            float4 b0 = *(const float4*)&Ws[(txc +  0)*RS + u*4];
            float4 b1 = *(const float4*)&Ws[(txc + 16)*RS + u*4];
            float4 b2 = *(const float4*)&Ws[(txc + 32)*RS + u*4];
            float4 b3 = *(const float4*)&Ws[(txc + 48)*RS + u*4];
            const ull* A0 = (const ull*)&a0; const ull* A1 = (const ull*)&a1;
            const ull* A2 = (const ull*)&a2; const ull* A3 = (const ull*)&a3;
            const ull* B0 = (const ull*)&b0; const ull* B1 = (const ull*)&b1;
            const ull* B2 = (const ull*)&b2; const ull* B3 = (const ull*)&b3;
#pragma unroll
            for (int h = 0; h < 2; h++) {
                acc[0][0]=fma2(A0[h],B0[h],acc[0][0]); acc[0][1]=fma2(A0[h],B1[h],acc[0][1]);
                acc[0][2]=fma2(A0[h],B2[h],acc[0][2]); acc[0][3]=fma2(A0[h],B3[h],acc[0][3]);
                acc[1][0]=fma2(A1[h],B0[h],acc[1][0]); acc[1][1]=fma2(A1[h],B1[h],acc[1][1]);
                acc[1][2]=fma2(A1[h],B2[h],acc[1][2]); acc[1][3]=fma2(A1[h],B3[h],acc[1][3]);
                acc[2][0]=fma2(A2[h],B0[h],acc[2][0]); acc[2][1]=fma2(A2[h],B1[h],acc[2][1]);
                acc[2][2]=fma2(A2[h],B2[h],acc[2][2]); acc[2][3]=fma2(A2[h],B3[h],acc[2][3]);
                acc[3][0]=fma2(A3[h],B0[h],acc[3][0]); acc[3][1]=fma2(A3[h],B1[h],acc[3][1]);
                acc[3][2]=fma2(A3[h],B2[h],acc[3][2]); acc[3][3]=fma2(A3[h],B3[h],acc[3][3]);
            }
        }

#pragma unroll
        for (int i = 0; i < 4; i++)
#pragma unroll
            for (int c = 0; c < 4; c++) {
                int col = cc*64 + txc + 16*c;
                Y[(row0 + ty*4 + i)*DQK + col] = pairsum(acc[i][c]) + bias[col];
            }
    }
}

// ---------------------------------------------------------------------------
// Inline candidate merge (static indexing) + gather K/V + softmax + V sum.
__global__ __launch_bounds__(256) void attn_kernel(float* __restrict__ out) {
    int gw   = (blockIdx.x * 256 + threadIdx.x) >> 5;
    int lane = threadIdx.x & 31;
    if (gw >= NTOT) return;

    // merge NSPLIT candidate lists (value desc, index asc), replicated per lane
    float cv[NSPLIT*KTOP]; int cj[NSPLIT*KTOP];
#pragma unroll
    for (int p = 0; p < NSPLIT; p++)
#pragma unroll
        for (int s = 0; s < KTOP; s++) {
            cv[p*KTOP+s] = g_cv[(p*NTOT + gw)*KTOP + s];
            cj[p*KTOP+s] = g_cj[(p*NTOT + gw)*KTOP + s];
        }
    int idx[KTOP];
#pragma unroll
    for (int s = 0; s < KTOP; s++) {
        float bv = cv[0]; int bj = cj[0]; int bp = 0;
#pragma unroll
        for (int t = 1; t < NSPLIT*KTOP; t++)
            if (cv[t] > bv || (cv[t] == bv && cj[t] < bj)) { bv = cv[t]; bj = cj[t]; bp = t; }
        idx[s] = bj;
#pragma unroll
        for (int t = 0; t < NSPLIT*KTOP; t++)
            if (t == bp) { cv[t] = -INFINITY; cj[t] = 0x7fffffff; }
    }

    const float4* q4 = (const float4*)(g_q + gw*DQK);
    float4 qa = q4[lane*2], qb = q4[lane*2 + 1];

    float s[KTOP];
#pragma unroll
    for (int k = 0; k < KTOP; k++) {
        const float4* k4 = (const float4*)(g_k + idx[k]*DQK);
        float4 ka = k4[lane*2], kb = k4[lane*2 + 1];
        float p = qa.x*ka.x + qa.y*ka.y + qa.z*ka.z + qa.w*ka.w
                + qb.x*kb.x + qb.y*kb.y + qb.z*kb.z + qb.w*kb.w;
#pragma unroll
        for (int off = 16; off; off >>= 1) p += __shfl_xor_sync(0xffffffffu, p, off);
        s[k] = p * (1.0f / 16.0f);
    }

    float m = s[0];
#pragma unroll
    for (int k = 1; k < KTOP; k++) m = fmaxf(m, s[k]);
    float esum = 0.f;
#pragma unroll
    for (int k = 0; k < KTOP; k++) { s[k] = expf(s[k] - m); esum += s[k]; }
    float inv = 1.f / esum;

    float4 oa = make_float4(0.f,0.f,0.f,0.f), ob = make_float4(0.f,0.f,0.f,0.f);
#pragma unroll
    for (int k = 0; k < KTOP; k++) {
        const float4* v4 = (const float4*)(g_v + idx[k]*DQK);
        float4 va = v4[lane*2], vb = v4[lane*2 + 1];
        float a = s[k] * inv;
        oa.x += a*va.x; oa.y += a*va.y; oa.z += a*va.z; oa.w += a*va.w;
        ob.x += a*vb.x; ob.y += a*vb.y; ob.z += a*vb.z; ob.w += a*vb.w;
    }
    float4* o4 = (float4*)(out + gw*DQK);
    o4[lane*2] = oa; o4[lane*2 + 1] = ob;
}

// ---------------------------------------------------------------------------
extern "C" void kernel_launch(void* const* d_in, const int* in_sizes, int n_in,
                              void* d_out, int out_size) {
    const float* ue = (const float*)d_in[0];
    const float* ie = (const float*)d_in[1];
    const int*   nr = (const int*)d_in[2];
    const int*   nc = (const int*)d_in[3];
    const float* nv = (const float*)d_in[4];
    const int*   ar = (const int*)d_in[5];
    const int*   ac = (const int*)d_in[6];
    const float* av = (const float*)d_in[7];
    const float* Wq = (const float*)d_in[8];
    const float* bq = (const float*)d_in[9];
    const float* Wk = (const float*)d_in[10];
    const float* bk = (const float*)d_in[11];
    const float* Wv = (const float*)d_in[12];
    const float* bv = (const float*)d_in[13];
    float* out = (float*)d_out;

    int nnz = in_sizes[2];
    int ew_blocks   = (NTOT*EDIM + 255) / 256;
    int spmm_blocks = (nnz*16 + 255) / 256;
    int es_bytes    = 2 * TJ * RS * sizeof(float);

    cudaFuncSetAttribute(topk_pass, cudaFuncAttributeMaxDynamicSharedMemorySize, es_bytes);

    float *ego0, *ego1, *ego2, *B;
    cudaGetSymbolAddress((void**)&ego0, g_ego0);
    cudaGetSymbolAddress((void**)&ego1, g_ego1);
    cudaGetSymbolAddress((void**)&ego2, g_ego2);
    cudaGetSymbolAddress((void**)&B,    g_B);

    init_kernel<<<ew_blocks, 256>>>(ue, ie);                                // #1
    spmm_atomic<<<spmm_blocks, 256>>>(nr, nc, nv, ego0, ego1, 1.0f, nnz);   // #2 ego1=An@ego0
    spmm_atomic<<<spmm_blocks, 256>>>(nr, nc, nv, ego1, ego2, 1.0f, nnz);   // #3 ego2=An@ego1
    qkv_kernel<<<dim3(NTOT/64, 3), 256>>>(Wq, bq, Wk, bk, Wv, bv);          // #4  <-- PROFILED
    spmm_atomic<<<spmm_blocks, 256>>>(ar, ac, av, ego2, B, 0.5f, nnz);      // #5 B=0.5*A@ego2
    topk_pass<<<dim3(NTOT/32, NSPLIT), 256, es_bytes>>>();                  // #6 sim + top5
    attn_kernel<<<(NTOT*32 + 255)/256, 256>>>(out + NTOT*EDIM);             // #7 merge+attn
    mean_kernel<<<ew_blocks, 256>>>(out);                                   // #8
}